// round 3
// baseline (speedup 1.0000x reference)
#include <cuda_runtime.h>
#include <math.h>

#define NKEYS 131072
#define DDIM 128
#define MDIM 128
#define QDIM 512
#define KTOT 256          // concatenated K dimension: [d | m]
#define KB 16             // keys per preprocessing block

// Scratch (static device globals — no runtime allocation).
// g_B row n: [0:128) = vn * x_mse   ;  [128:256) = sign(proj) * vn * rn * sqrt(pi/2)/m
// g_A row q: [0:128) = query[q]     ;  [128:256) = Sq[q] = query[q] @ S^T
__device__ float g_B[(size_t)NKEYS * KTOT];   // 128 MB
__device__ float g_A[(size_t)QDIM * KTOT];    // 512 KB

// ---------------------------------------------------------------------------
// Kernel 1: build A = [query | query @ S^T]
// grid = (512), block = 128. Thread j computes Sq[q][j].
// ---------------------------------------------------------------------------
__global__ void build_A_kernel(const float* __restrict__ query,
                               const float* __restrict__ S) {
    __shared__ float qsh[DDIM];
    int q = blockIdx.x;
    int j = threadIdx.x;
    float qv = query[q * DDIM + j];
    qsh[j] = qv;
    __syncthreads();
    const float* Srow = S + j * DDIM;
    float acc = 0.f;
#pragma unroll 8
    for (int i = 0; i < DDIM; i++) acc += qsh[i] * Srow[i];
    g_A[(size_t)q * KTOT + j] = qv;
    g_A[(size_t)q * KTOT + DDIM + j] = acc;
}

// ---------------------------------------------------------------------------
// Kernel 2: per-key preprocessing → g_B
// block = 128 threads, KB=16 keys/block, grid = NKEYS/KB = 8192.
// S is staged transposed in shared (stride 132: float4-aligned, conflict-free
// reads). Each warp projects 4 keys: lane holds 4 consecutive j-outputs.
// ---------------------------------------------------------------------------
__global__ __launch_bounds__(128) void prep_keys_kernel(
    const float* __restrict__ keys, const float* __restrict__ codebook,
    const float* __restrict__ S) {
    extern __shared__ float sh[];
    float* St   = sh;                    // [128][132]  St[i*132+j] = S[j][i]
    float* rsh  = sh + 128 * 132;        // [KB][128]   residuals
    float* c2sh = rsh + KB * 128;        // [KB]        vn*rn*scale
    __shared__ float red[4];

    int tid  = threadIdx.x;
    int lane = tid & 31;
    int w    = tid >> 5;

    float c0 = codebook[0], c1 = codebook[1], c2v = codebook[2], c3 = codebook[3];
    float m01 = 0.5f * (c0 + c1), m12 = 0.5f * (c1 + c2v), m23 = 0.5f * (c2v + c3);

    // Stage S transposed (coalesced global reads).
    for (int idx = tid; idx < DDIM * MDIM; idx += 128) {
        int j = idx >> 7;
        int i = idx & 127;
        St[i * 132 + j] = S[idx];
    }

    size_t n0 = (size_t)blockIdx.x * KB;
    const float scale = 0.009797554543986288f;  // sqrt(pi/2) / 128

    for (int k = 0; k < KB; k++) {
        size_t n = n0 + (size_t)k;
        float kv = keys[n * DDIM + tid];

        float s = kv * kv;
#pragma unroll
        for (int o = 16; o; o >>= 1) s += __shfl_xor_sync(0xffffffffu, s, o);
        if (lane == 0) red[w] = s;
        __syncthreads();
        float vn = sqrtf(red[0] + red[1] + red[2] + red[3]);
        __syncthreads();

        float x  = kv / (vn + 1e-8f);
        // nearest of 4 sorted centers via midpoint compares
        float xm = (x >= m12) ? ((x >= m23) ? c3 : c2v)
                              : ((x >= m01) ? c1 : c0);
        float r = x - xm;

        float s2 = r * r;
#pragma unroll
        for (int o = 16; o; o >>= 1) s2 += __shfl_xor_sync(0xffffffffu, s2, o);
        if (lane == 0) red[w] = s2;
        __syncthreads();
        float rn = sqrtf(red[0] + red[1] + red[2] + red[3]);
        __syncthreads();

        g_B[n * KTOT + tid] = vn * xm;
        rsh[k * 128 + tid] = r;
        if (tid == 0) c2sh[k] = vn * rn * scale;
    }
    __syncthreads();

    // Projection: warp w handles keys [w*4, w*4+4); lane covers j = lane*4..+3.
    float acc[4][4];
#pragma unroll
    for (int a = 0; a < 4; a++)
#pragma unroll
        for (int b = 0; b < 4; b++) acc[a][b] = 0.f;

    int jb = lane * 4;
    const float* rbase = rsh + (w * 4) * 128;
#pragma unroll 4
    for (int i = 0; i < 128; i++) {
        float4 sv = *(const float4*)&St[i * 132 + jb];
#pragma unroll
        for (int kk = 0; kk < 4; kk++) {
            float rv = rbase[kk * 128 + i];   // broadcast LDS
            acc[kk][0] += sv.x * rv;
            acc[kk][1] += sv.y * rv;
            acc[kk][2] += sv.z * rv;
            acc[kk][3] += sv.w * rv;
        }
    }
#pragma unroll
    for (int kk = 0; kk < 4; kk++) {
        size_t n = n0 + (size_t)(w * 4 + kk);
        float cc = c2sh[w * 4 + kk];
        float4 o;
        o.x = (acc[kk][0] >= 0.f) ? cc : -cc;
        o.y = (acc[kk][1] >= 0.f) ? cc : -cc;
        o.z = (acc[kk][2] >= 0.f) ? cc : -cc;
        o.w = (acc[kk][3] >= 0.f) ? cc : -cc;
        *(float4*)&g_B[n * KTOT + DDIM + jb] = o;
    }
}

// ---------------------------------------------------------------------------
// Kernel 3: out(512 x 131072) = A(512x256) @ B(131072x256)^T, fp32
// 128x128x16 tiles, 256 threads, 8x8 micro-tiles. Shared stride 132 (pad).
// ---------------------------------------------------------------------------
#define BM 128
#define BN 128
#define BKC 16

__global__ __launch_bounds__(256) void gemm_kernel(float* __restrict__ out) {
    __shared__ float As[BKC][132];
    __shared__ float Bs[BKC][132];
    int tid = threadIdx.x;
    int tx = tid & 15;
    int ty = tid >> 4;
    size_t n0 = (size_t)blockIdx.x * BN;
    size_t q0 = (size_t)blockIdx.y * BM;
    const float* Aptr = g_A + q0 * KTOT;
    const float* Bptr = g_B + n0 * KTOT;

    float acc[8][8];
#pragma unroll
    for (int i = 0; i < 8; i++)
#pragma unroll
        for (int j = 0; j < 8; j++) acc[i][j] = 0.f;

    for (int k0 = 0; k0 < KTOT; k0 += BKC) {
#pragma unroll
        for (int it = 0; it < 2; it++) {
            int idx = tid + it * 256;        // 0..511 over (row, 4x float4)
            int row = idx >> 2;
            int c = (idx & 3) * 4;
            float4 a = *(const float4*)&Aptr[(size_t)row * KTOT + k0 + c];
            As[c + 0][row] = a.x; As[c + 1][row] = a.y;
            As[c + 2][row] = a.z; As[c + 3][row] = a.w;
            float4 b = *(const float4*)&Bptr[(size_t)row * KTOT + k0 + c];
            Bs[c + 0][row] = b.x; Bs[c + 1][row] = b.y;
            Bs[c + 2][row] = b.z; Bs[c + 3][row] = b.w;
        }
        __syncthreads();
#pragma unroll
        for (int kk = 0; kk < BKC; kk++) {
            float a[8], b[8];
            *(float4*)&a[0] = *(const float4*)&As[kk][ty * 8];
            *(float4*)&a[4] = *(const float4*)&As[kk][ty * 8 + 4];
            *(float4*)&b[0] = *(const float4*)&Bs[kk][tx * 8];
            *(float4*)&b[4] = *(const float4*)&Bs[kk][tx * 8 + 4];
#pragma unroll
            for (int i = 0; i < 8; i++)
#pragma unroll
                for (int j = 0; j < 8; j++)
                    acc[i][j] += a[i] * b[j];
        }
        __syncthreads();
    }

#pragma unroll
    for (int i = 0; i < 8; i++) {
        size_t row = q0 + (size_t)(ty * 8 + i);
        float* op = out + row * NKEYS + n0 + (size_t)(tx * 8);
        *(float4*)&op[0] = make_float4(acc[i][0], acc[i][1], acc[i][2], acc[i][3]);
        *(float4*)&op[4] = make_float4(acc[i][4], acc[i][5], acc[i][6], acc[i][7]);
    }
}

// ---------------------------------------------------------------------------
extern "C" void kernel_launch(void* const* d_in, const int* in_sizes, int n_in,
                              void* d_out, int out_size) {
    const float* query    = (const float*)d_in[0];
    const float* keys     = (const float*)d_in[1];
    const float* codebook = (const float*)d_in[2];
    const float* S        = (const float*)d_in[3];
    float* out = (float*)d_out;

    build_A_kernel<<<QDIM, 128>>>(query, S);

    size_t shbytes = (size_t)(128 * 132 + KB * 128 + KB) * sizeof(float);  // 75840 B
    cudaFuncSetAttribute(prep_keys_kernel,
                         cudaFuncAttributeMaxDynamicSharedMemorySize, (int)shbytes);
    prep_keys_kernel<<<NKEYS / KB, 128, shbytes>>>(keys, codebook, S);

    dim3 grid(NKEYS / BN, QDIM / BM);
    gemm_kernel<<<grid, 256>>>(out);
}

// round 6
// speedup vs baseline: 1.4704x; 1.4704x over previous
#include <cuda_runtime.h>
#include <cuda_bf16.h>
#include <math.h>
#include <stdint.h>

#define NKEYS 131072
#define DDIM 128
#define QDIM 512
#define KTOT 256
#define KB 16

__device__ __nv_bfloat16 g_Bh[(size_t)NKEYS * KTOT];
__device__ __nv_bfloat16 g_Bl[(size_t)NKEYS * KTOT];
__device__ __nv_bfloat16 g_Ah[(size_t)QDIM * KTOT];
__device__ __nv_bfloat16 g_Al[(size_t)QDIM * KTOT];

__device__ __forceinline__ uint32_t smem_u32(const void* p) {
    uint32_t a;
    asm("{ .reg .u64 t; cvta.to.shared.u64 t, %1; cvt.u32.u64 %0, t; }" : "=r"(a) : "l"(p));
    return a;
}
__device__ __forceinline__ void cp_async16(uint32_t dst, const void* src) {
    uint64_t g;
    asm("cvta.to.global.u64 %0, %1;" : "=l"(g) : "l"(src));
    asm volatile("cp.async.cg.shared.global [%0], [%1], 16;" :: "r"(dst), "l"(g));
}
#define CP_COMMIT() asm volatile("cp.async.commit_group;" ::: "memory")
#define CP_WAIT1()  asm volatile("cp.async.wait_group 1;" ::: "memory")
#define CP_WAIT0()  asm volatile("cp.async.wait_group 0;" ::: "memory")

__device__ __forceinline__ void ldsm4(uint32_t& r0, uint32_t& r1, uint32_t& r2,
                                      uint32_t& r3, uint32_t addr) {
    asm volatile("ldmatrix.sync.aligned.m8n8.x4.shared.b16 {%0,%1,%2,%3}, [%4];"
                 : "=r"(r0), "=r"(r1), "=r"(r2), "=r"(r3) : "r"(addr));
}
__device__ __forceinline__ void mma16816(float* c, uint32_t a0, uint32_t a1,
                                         uint32_t a2, uint32_t a3,
                                         uint32_t b0, uint32_t b1) {
    asm volatile(
        "mma.sync.aligned.m16n8k16.row.col.f32.bf16.bf16.f32 "
        "{%0,%1,%2,%3}, {%4,%5,%6,%7}, {%8,%9}, {%0,%1,%2,%3};"
        : "+f"(c[0]), "+f"(c[1]), "+f"(c[2]), "+f"(c[3])
        : "r"(a0), "r"(a1), "r"(a2), "r"(a3), "r"(b0), "r"(b1));
}
__device__ __forceinline__ void bf16split(float v, __nv_bfloat16& h, __nv_bfloat16& l) {
    h = __float2bfloat16(v);
    l = __float2bfloat16(v - __bfloat162float(h));
}

// --- Kernel 1: A = [query | query @ S^T] -> bf16 hi/lo. grid=64, block=256 ---
__global__ __launch_bounds__(256) void build_A_kernel(const float* __restrict__ query,
                                                      const float* __restrict__ S) {
    extern __shared__ float sh[];
    float* St = sh;                 // [i*129+j] = S[j][i]
    float* qsh = sh + 128 * 129;    // [2][128]
    int t = threadIdx.x, j = t & 127, qs = t >> 7;
    for (int idx = t; idx < 128 * 128; idx += 256) {
        int jj = idx >> 7, ii = idx & 127;
        St[ii * 129 + jj] = S[idx];
    }
    __syncthreads();
    int q0 = blockIdx.x * 8;
    for (int qq = 0; qq < 4; qq++) {
        int q = q0 + qq * 2 + qs;
        float qv = query[q * DDIM + j];
        qsh[qs * 128 + j] = qv;
        __syncthreads();
        float acc = 0.f;
#pragma unroll 8
        for (int i = 0; i < 128; i++) acc += qsh[qs * 128 + i] * St[i * 129 + j];
        __nv_bfloat16 h, l;
        bf16split(qv, h, l);
        g_Ah[(size_t)q * KTOT + j] = h; g_Al[(size_t)q * KTOT + j] = l;
        bf16split(acc, h, l);
        g_Ah[(size_t)q * KTOT + 128 + j] = h; g_Al[(size_t)q * KTOT + 128 + j] = l;
        __syncthreads();
    }
}

// --- Kernel 2: per-key prep -> g_Bh/g_Bl ---
__global__ __launch_bounds__(128) void prep_keys_kernel(
    const float* __restrict__ keys, const float* __restrict__ codebook,
    const float* __restrict__ S) {
    extern __shared__ float sh[];
    float* St = sh;                 // [128][132]
    float* rsh = sh + 128 * 132;    // [KB][128]
    float* c2sh = rsh + KB * 128;   // [KB]
    __shared__ float red[4];
    int tid = threadIdx.x, lane = tid & 31, w = tid >> 5;
    float c0 = codebook[0], c1 = codebook[1], c2v = codebook[2], c3 = codebook[3];
    float m01 = 0.5f * (c0 + c1), m12 = 0.5f * (c1 + c2v), m23 = 0.5f * (c2v + c3);
    for (int idx = tid; idx < DDIM * 128; idx += 128) {
        int j = idx >> 7, i = idx & 127;
        St[i * 132 + j] = S[idx];
    }
    size_t n0 = (size_t)blockIdx.x * KB;
    const float scale = 0.009797554543986288f;  // sqrt(pi/2)/128
    for (int k = 0; k < KB; k++) {
        size_t n = n0 + (size_t)k;
        float kv = keys[n * DDIM + tid];
        float s = kv * kv;
#pragma unroll
        for (int o = 16; o; o >>= 1) s += __shfl_xor_sync(0xffffffffu, s, o);
        if (lane == 0) red[w] = s;
        __syncthreads();
        float vn = sqrtf(red[0] + red[1] + red[2] + red[3]);
        __syncthreads();
        float x = kv / (vn + 1e-8f);
        float xm = (x >= m12) ? ((x >= m23) ? c3 : c2v) : ((x >= m01) ? c1 : c0);
        float r = x - xm;
        float s2 = r * r;
#pragma unroll
        for (int o = 16; o; o >>= 1) s2 += __shfl_xor_sync(0xffffffffu, s2, o);
        if (lane == 0) red[w] = s2;
        __syncthreads();
        float rn = sqrtf(red[0] + red[1] + red[2] + red[3]);
        __syncthreads();
        __nv_bfloat16 h, l;
        bf16split(vn * xm, h, l);
        g_Bh[n * KTOT + tid] = h; g_Bl[n * KTOT + tid] = l;
        rsh[k * 128 + tid] = r;
        if (tid == 0) c2sh[k] = vn * rn * scale;
    }
    __syncthreads();
    float acc[4][4];
#pragma unroll
    for (int a = 0; a < 4; a++)
#pragma unroll
        for (int b = 0; b < 4; b++) acc[a][b] = 0.f;
    int jb = lane * 4;
    const float* rbase = rsh + (w * 4) * 128;
#pragma unroll 4
    for (int i = 0; i < 128; i++) {
        float4 sv = *(const float4*)&St[i * 132 + jb];
#pragma unroll
        for (int kk = 0; kk < 4; kk++) {
            float rv = rbase[kk * 128 + i];
            acc[kk][0] += sv.x * rv; acc[kk][1] += sv.y * rv;
            acc[kk][2] += sv.z * rv; acc[kk][3] += sv.w * rv;
        }
    }
#pragma unroll
    for (int kk = 0; kk < 4; kk++) {
        size_t n = n0 + (size_t)(w * 4 + kk);
        float cc = c2sh[w * 4 + kk];
        __nv_bfloat16 ch, cl;
        bf16split(cc, ch, cl);
        union { __nv_bfloat16 b[4]; uint2 u; } ph, pl;
#pragma unroll
        for (int jj = 0; jj < 4; jj++) {
            bool pos = (acc[kk][jj] >= 0.f);
            ph.b[jj] = pos ? ch : __hneg(ch);
            pl.b[jj] = pos ? cl : __hneg(cl);
        }
        *(uint2*)&g_Bh[n * KTOT + 128 + jb] = ph.u;
        *(uint2*)&g_Bl[n * KTOT + 128 + jb] = pl.u;
    }
}

// --- Kernel 3: mma.sync bf16 GEMM, 3-term split ---
// CTA: 128x128, 8 warps (2Mx4N), warp 64x32. K chunks of 64, double buffered.
// Stage layout (row-padded 144B): AH | AL | BH | BL, each 128x144B.
#define ROWB 144
#define ARR  18432     // 128*144
#define STG  73728     // 4*ARR

__global__ __launch_bounds__(256, 1) void gemm_kernel(float* __restrict__ out) {
    extern __shared__ __align__(16) char sm[];
    uint32_t sbase = smem_u32(sm);
    int tid = threadIdx.x, wid = tid >> 5, lane = tid & 31;
    int wm = wid >> 2, wn = wid & 3;
    size_t q0 = (size_t)blockIdx.x * 128;
    size_t n0 = (size_t)blockIdx.y * 128;

    float acc[4][4][4];
#pragma unroll
    for (int i = 0; i < 4; i++)
#pragma unroll
        for (int j = 0; j < 4; j++)
#pragma unroll
            for (int k = 0; k < 4; k++) acc[i][j][k] = 0.f;

    // ---- stage fill helper (inlined manually) ----
#define LOAD_STAGE(KC, S_)                                                     \
    do {                                                                       \
        uint32_t stg_ = sbase + (S_) * STG;                                    \
        int kofs_ = (KC) * 64;                                                 \
        _Pragma("unroll")                                                      \
        for (int it = 0; it < 4; it++) {                                       \
            int idx = tid + it * 256;                                          \
            int row = idx >> 3, c16 = idx & 7;                                 \
            uint32_t d = (uint32_t)(row * ROWB + c16 * 16);                    \
            size_t ao = (q0 + (size_t)row) * KTOT + kofs_ + c16 * 8;           \
            cp_async16(stg_ + d,           g_Ah + ao);                         \
            cp_async16(stg_ + ARR + d,     g_Al + ao);                         \
            size_t bo = (n0 + (size_t)row) * KTOT + kofs_ + c16 * 8;           \
            cp_async16(stg_ + 2 * ARR + d, g_Bh + bo);                         \
            cp_async16(stg_ + 3 * ARR + d, g_Bl + bo);                         \
        }                                                                      \
        CP_COMMIT();                                                           \
    } while (0)

    LOAD_STAGE(0, 0);

    int lr = lane & 15;            // ldmatrix row-within-16
    int lc = (lane >> 4) * 8;      // ldmatrix col offset (elements)

    for (int kc = 0; kc < 4; kc++) {
        if (kc < 3) { LOAD_STAGE(kc + 1, (kc + 1) & 1); CP_WAIT1(); }
        else        { CP_WAIT0(); }
        __syncthreads();
        uint32_t stg = sbase + (kc & 1) * STG;
        uint32_t arow[4], brow[2];
#pragma unroll
        for (int mi = 0; mi < 4; mi++)
            arow[mi] = stg + (uint32_t)((wm * 64 + mi * 16 + lr) * ROWB);
#pragma unroll
        for (int h = 0; h < 2; h++)
            brow[h] = stg + 2 * ARR + (uint32_t)((wn * 32 + h * 16 + lr) * ROWB);

#pragma unroll
        for (int ks = 0; ks < 4; ks++) {
            uint32_t coff = (uint32_t)((ks * 16 + lc) * 2);
            uint32_t ah[4][4], al[4][4], bh[8], bl[8];
#pragma unroll
            for (int mi = 0; mi < 4; mi++) {
                uint32_t ad = arow[mi] + coff;
                ldsm4(ah[mi][0], ah[mi][1], ah[mi][2], ah[mi][3], ad);
                ldsm4(al[mi][0], al[mi][1], al[mi][2], al[mi][3], ad + ARR);
            }
#pragma unroll
            for (int h = 0; h < 2; h++) {
                uint32_t bd = brow[h] + coff;
                ldsm4(bh[h * 4 + 0], bh[h * 4 + 1], bh[h * 4 + 2], bh[h * 4 + 3], bd);
                ldsm4(bl[h * 4 + 0], bl[h * 4 + 1], bl[h * 4 + 2], bl[h * 4 + 3], bd + ARR);
            }
#pragma unroll
            for (int mi = 0; mi < 4; mi++)
#pragma unroll
                for (int ni = 0; ni < 4; ni++) {
                    int h = ni >> 1, s2 = ni & 1;
                    uint32_t b0h = bh[h * 4 + s2], b1h = bh[h * 4 + s2 + 2];
                    uint32_t b0l = bl[h * 4 + s2], b1l = bl[h * 4 + s2 + 2];
                    mma16816(acc[mi][ni], ah[mi][0], ah[mi][1], ah[mi][2], ah[mi][3], b0h, b1h);
                    mma16816(acc[mi][ni], al[mi][0], al[mi][1], al[mi][2], al[mi][3], b0h, b1h);
                    mma16816(acc[mi][ni], ah[mi][0], ah[mi][1], ah[mi][2], ah[mi][3], b0l, b1l);
                }
        }
        __syncthreads();
    }

    // Epilogue: mma C layout -> global float2 stores
    int g = lane >> 2, tc = lane & 3;
#pragma unroll
    for (int mi = 0; mi < 4; mi++) {
        size_t r0 = q0 + (size_t)(wm * 64 + mi * 16 + g);
        size_t r1 = r0 + 8;
#pragma unroll
        for (int ni = 0; ni < 4; ni++) {
            size_t col = n0 + (size_t)(wn * 32 + ni * 8 + tc * 2);
            *(float2*)(out + r0 * NKEYS + col) = make_float2(acc[mi][ni][0], acc[mi][ni][1]);
            *(float2*)(out + r1 * NKEYS + col) = make_float2(acc[mi][ni][2], acc[mi][ni][3]);
        }
    }
}

extern "C" void kernel_launch(void* const* d_in, const int* in_sizes, int n_in,
                              void* d_out, int out_size) {
    const float* query    = (const float*)d_in[0];
    const float* keys     = (const float*)d_in[1];
    const float* codebook = (const float*)d_in[2];
    const float* S        = (const float*)d_in[3];
    float* out = (float*)d_out;

    int shA = (128 * 129 + 256) * 4;
    cudaFuncSetAttribute(build_A_kernel, cudaFuncAttributeMaxDynamicSharedMemorySize, shA);
    build_A_kernel<<<64, 256, shA>>>(query, S);

    int shP = (128 * 132 + KB * 128 + KB) * 4;
    cudaFuncSetAttribute(prep_keys_kernel, cudaFuncAttributeMaxDynamicSharedMemorySize, shP);
    prep_keys_kernel<<<NKEYS / KB, 128, shP>>>(keys, codebook, S);

    int shG = 2 * STG;  // 147456
    cudaFuncSetAttribute(gemm_kernel, cudaFuncAttributeMaxDynamicSharedMemorySize, shG);
    dim3 grid(QDIM / 128, NKEYS / 128);
    gemm_kernel<<<grid, 256, shG>>>(out);
}

// round 8
// speedup vs baseline: 2.6880x; 1.8281x over previous
#include <cuda_runtime.h>
#include <cuda_bf16.h>
#include <math.h>
#include <stdint.h>

#define NKEYS 131072
#define DDIM 128
#define QDIM 512
#define KTOT 256
#define MAXQ 262144
#define SIGN_TH 5e-4f

__device__ __nv_bfloat16 g_Bh[(size_t)NKEYS * KTOT];
__device__ __nv_bfloat16 g_Bl[(size_t)NKEYS * KTOT];
__device__ __nv_bfloat16 g_Rh[(size_t)NKEYS * DDIM];
__device__ __nv_bfloat16 g_Rl[(size_t)NKEYS * DDIM];
__device__ float         g_C [(size_t)NKEYS];
__device__ float         g_Rn[(size_t)NKEYS];
__device__ __nv_bfloat16 g_Sh[DDIM * DDIM];
__device__ __nv_bfloat16 g_Sl[DDIM * DDIM];
__device__ __nv_bfloat16 g_Ah[(size_t)QDIM * KTOT];
__device__ __nv_bfloat16 g_Al[(size_t)QDIM * KTOT];
__device__ int           g_qcount;
__device__ uint32_t      g_queue[MAXQ];

__device__ __forceinline__ uint32_t smem_u32(const void* p) {
    uint32_t a;
    asm("{ .reg .u64 t; cvta.to.shared.u64 t, %1; cvt.u32.u64 %0, t; }" : "=r"(a) : "l"(p));
    return a;
}
__device__ __forceinline__ void cp_async16(uint32_t dst, const void* src) {
    uint64_t g;
    asm("cvta.to.global.u64 %0, %1;" : "=l"(g) : "l"(src));
    asm volatile("cp.async.cg.shared.global [%0], [%1], 16;" :: "r"(dst), "l"(g));
}
#define CP_COMMIT() asm volatile("cp.async.commit_group;" ::: "memory")
#define CP_WAIT1()  asm volatile("cp.async.wait_group 1;" ::: "memory")
#define CP_WAIT0()  asm volatile("cp.async.wait_group 0;" ::: "memory")

__device__ __forceinline__ void ldsm4(uint32_t& r0, uint32_t& r1, uint32_t& r2,
                                      uint32_t& r3, uint32_t addr) {
    asm volatile("ldmatrix.sync.aligned.m8n8.x4.shared.b16 {%0,%1,%2,%3}, [%4];"
                 : "=r"(r0), "=r"(r1), "=r"(r2), "=r"(r3) : "r"(addr));
}
__device__ __forceinline__ void mma16816(float* c, uint32_t a0, uint32_t a1,
                                         uint32_t a2, uint32_t a3,
                                         uint32_t b0, uint32_t b1) {
    asm volatile(
        "mma.sync.aligned.m16n8k16.row.col.f32.bf16.bf16.f32 "
        "{%0,%1,%2,%3}, {%4,%5,%6,%7}, {%8,%9}, {%0,%1,%2,%3};"
        : "+f"(c[0]), "+f"(c[1]), "+f"(c[2]), "+f"(c[3])
        : "r"(a0), "r"(a1), "r"(a2), "r"(a3), "r"(b0), "r"(b1));
}
__device__ __forceinline__ void bf16split(float v, __nv_bfloat16& h, __nv_bfloat16& l) {
    h = __float2bfloat16(v);
    l = __float2bfloat16(v - __bfloat162float(h));
}
__device__ __forceinline__ uint32_t pack2(__nv_bfloat16 a, __nv_bfloat16 b) {
    union { __nv_bfloat16 h[2]; uint32_t u; } t;
    t.h[0] = a; t.h[1] = b;
    return t.u;
}
__device__ __forceinline__ void enqueue(uint32_t n, uint32_t j) {
    uint32_t idx = (uint32_t)atomicAdd(&g_qcount, 1);
    if (idx < MAXQ) g_queue[idx] = (n << 7) | j;
}

// --- reset queue counter ---
__global__ void zeroq_kernel() { if (threadIdx.x == 0) g_qcount = 0; }

// --- S fp32 -> bf16 hi/lo ---
__global__ void build_S_kernel(const float* __restrict__ S) {
    int i = blockIdx.x * 256 + threadIdx.x;
    __nv_bfloat16 h, l;
    bf16split(S[i], h, l);
    g_Sh[i] = h; g_Sl[i] = l;
}

// --- A = [query | query @ S^T] -> bf16 hi/lo ---
__global__ __launch_bounds__(256) void build_A_kernel(const float* __restrict__ query,
                                                      const float* __restrict__ S) {
    extern __shared__ float sh[];
    float* St = sh;                 // [i*129+j] = S[j][i]
    float* qsh = sh + 128 * 129;
    int t = threadIdx.x, j = t & 127, qs = t >> 7;
    for (int idx = t; idx < 128 * 128; idx += 256) {
        int jj = idx >> 7, ii = idx & 127;
        St[ii * 129 + jj] = S[idx];
    }
    __syncthreads();
    int q0 = blockIdx.x * 8;
    for (int qq = 0; qq < 4; qq++) {
        int q = q0 + qq * 2 + qs;
        float qv = query[q * DDIM + j];
        qsh[qs * 128 + j] = qv;
        __syncthreads();
        float acc = 0.f;
#pragma unroll 8
        for (int i = 0; i < 128; i++) acc += qsh[qs * 128 + i] * St[i * 129 + j];
        __nv_bfloat16 h, l;
        bf16split(qv, h, l);
        g_Ah[(size_t)q * KTOT + j] = h; g_Al[(size_t)q * KTOT + j] = l;
        bf16split(acc, h, l);
        g_Ah[(size_t)q * KTOT + 128 + j] = h; g_Al[(size_t)q * KTOT + 128 + j] = l;
        __syncthreads();
    }
}

// --- prep1: warp-per-key, no block syncs ---
__global__ __launch_bounds__(256) void prep1_kernel(const float* __restrict__ keys,
                                                    const float* __restrict__ cb) {
    int lane = threadIdx.x & 31, w = threadIdx.x >> 5;
    size_t n = (size_t)blockIdx.x * 8 + w;
    float c0 = cb[0], c1 = cb[1], c2 = cb[2], c3 = cb[3];
    float m01 = 0.5f * (c0 + c1), m12 = 0.5f * (c1 + c2), m23 = 0.5f * (c2 + c3);

    float4 kv = *(const float4*)(keys + n * DDIM + lane * 4);
    float ss = kv.x * kv.x + kv.y * kv.y + kv.z * kv.z + kv.w * kv.w;
#pragma unroll
    for (int o = 16; o; o >>= 1) ss += __shfl_xor_sync(0xffffffffu, ss, o);
    float vn = sqrtf(ss);
    float inv = 1.f / (vn + 1e-8f);

    float x[4] = {kv.x * inv, kv.y * inv, kv.z * inv, kv.w * inv};
    float r[4], rr = 0.f;
    __nv_bfloat16 th[4], tl[4];
#pragma unroll
    for (int i = 0; i < 4; i++) {
        float xm = (x[i] >= m12) ? ((x[i] >= m23) ? c3 : c2)
                                 : ((x[i] >= m01) ? c1 : c0);
        r[i] = x[i] - xm;
        rr += r[i] * r[i];
        bf16split(vn * xm, th[i], tl[i]);
    }
    *(uint2*)&g_Bh[n * KTOT + lane * 4] = make_uint2(pack2(th[0], th[1]), pack2(th[2], th[3]));
    *(uint2*)&g_Bl[n * KTOT + lane * 4] = make_uint2(pack2(tl[0], tl[1]), pack2(tl[2], tl[3]));

#pragma unroll
    for (int o = 16; o; o >>= 1) rr += __shfl_xor_sync(0xffffffffu, rr, o);
    float rn = sqrtf(rr);

    __nv_bfloat16 rh[4], rl[4];
#pragma unroll
    for (int i = 0; i < 4; i++) bf16split(r[i], rh[i], rl[i]);
    *(uint2*)&g_Rh[n * DDIM + lane * 4] = make_uint2(pack2(rh[0], rh[1]), pack2(rh[2], rh[3]));
    *(uint2*)&g_Rl[n * DDIM + lane * 4] = make_uint2(pack2(rl[0], rl[1]), pack2(rl[2], rl[3]));
    if (lane == 0) {
        g_C[n]  = vn * rn * 0.009797554543986288f;  // sqrt(pi/2)/128
        g_Rn[n] = rn;
    }
}

// --- proj: sign(R @ S^T)*coef -> g_B[:,128:256]; enqueue ambiguous signs ---
#define PROW 272
#define PARR 34816    // 128*272

__global__ __launch_bounds__(256, 1) void proj_kernel() {
    extern __shared__ __align__(16) char sm[];
    uint32_t sb = smem_u32(sm);
    int tid = threadIdx.x, wid = tid >> 5, lane = tid & 31;
    int wm = wid >> 2, wn = wid & 3;
    size_t n0 = (size_t)blockIdx.x * 128;

#pragma unroll
    for (int it = 0; it < 8; it++) {
        int idx = tid + it * 256;
        int row = idx >> 4, c16 = idx & 15;
        uint32_t d = (uint32_t)(row * PROW + c16 * 16);
        size_t ro = (n0 + (size_t)row) * DDIM + c16 * 8;
        cp_async16(sb + d,            g_Rh + ro);
        cp_async16(sb + PARR + d,     g_Rl + ro);
        size_t so = (size_t)row * DDIM + c16 * 8;
        cp_async16(sb + 2 * PARR + d, g_Sh + so);
        cp_async16(sb + 3 * PARR + d, g_Sl + so);
    }
    CP_COMMIT();

    float acc[4][4][4];
#pragma unroll
    for (int i = 0; i < 4; i++)
#pragma unroll
        for (int j = 0; j < 4; j++)
#pragma unroll
            for (int k = 0; k < 4; k++) acc[i][j][k] = 0.f;

    CP_WAIT0();
    __syncthreads();

    int lr = lane & 15, lc = (lane >> 4) * 8;
#pragma unroll
    for (int ks = 0; ks < 8; ks++) {
        uint32_t coff = (uint32_t)((ks * 16 + lc) * 2);
        uint32_t bh[8], bl[8];
#pragma unroll
        for (int h = 0; h < 2; h++) {
            uint32_t bd = sb + 2 * PARR + (uint32_t)((wn * 32 + h * 16 + lr) * PROW) + coff;
            ldsm4(bh[h * 4 + 0], bh[h * 4 + 1], bh[h * 4 + 2], bh[h * 4 + 3], bd);
            ldsm4(bl[h * 4 + 0], bl[h * 4 + 1], bl[h * 4 + 2], bl[h * 4 + 3], bd + PARR);
        }
#pragma unroll
        for (int mi = 0; mi < 4; mi++) {
            uint32_t ad = sb + (uint32_t)((wm * 64 + mi * 16 + lr) * PROW) + coff;
            uint32_t ah0, ah1, ah2, ah3, al0, al1, al2, al3;
            ldsm4(ah0, ah1, ah2, ah3, ad);
            ldsm4(al0, al1, al2, al3, ad + PARR);
#pragma unroll
            for (int ni = 0; ni < 4; ni++) {
                int h = ni >> 1, s2 = ni & 1;
                uint32_t b0h = bh[h * 4 + s2], b1h = bh[h * 4 + s2 + 2];
                uint32_t b0l = bl[h * 4 + s2], b1l = bl[h * 4 + s2 + 2];
                mma16816(acc[mi][ni], ah0, ah1, ah2, ah3, b0h, b1h);
                mma16816(acc[mi][ni], al0, al1, al2, al3, b0h, b1h);
                mma16816(acc[mi][ni], ah0, ah1, ah2, ah3, b0l, b1l);
            }
        }
    }

    int g = lane >> 2, tc = lane & 3;
#pragma unroll
    for (int mi = 0; mi < 4; mi++) {
        size_t r0 = n0 + (size_t)(wm * 64 + mi * 16 + g);
        size_t r1 = r0 + 8;
        float cA = g_C[r0], cB = g_C[r1];
        float tA = g_Rn[r0] * SIGN_TH, tB = g_Rn[r1] * SIGN_TH;
        __nv_bfloat16 cAh, cAl, cBh, cBl;
        bf16split(cA, cAh, cAl);
        bf16split(cB, cBh, cBl);
#pragma unroll
        for (int ni = 0; ni < 4; ni++) {
            int j0 = wn * 32 + ni * 8 + tc * 2;
            bool p0 = acc[mi][ni][0] >= 0.f, p1 = acc[mi][ni][1] >= 0.f;
            bool p2 = acc[mi][ni][2] >= 0.f, p3 = acc[mi][ni][3] >= 0.f;
            *(uint32_t*)&g_Bh[r0 * KTOT + 128 + j0] =
                pack2(p0 ? cAh : __hneg(cAh), p1 ? cAh : __hneg(cAh));
            *(uint32_t*)&g_Bl[r0 * KTOT + 128 + j0] =
                pack2(p0 ? cAl : __hneg(cAl), p1 ? cAl : __hneg(cAl));
            *(uint32_t*)&g_Bh[r1 * KTOT + 128 + j0] =
                pack2(p2 ? cBh : __hneg(cBh), p3 ? cBh : __hneg(cBh));
            *(uint32_t*)&g_Bl[r1 * KTOT + 128 + j0] =
                pack2(p2 ? cBl : __hneg(cBl), p3 ? cBl : __hneg(cBl));
            if (fabsf(acc[mi][ni][0]) < tA) enqueue((uint32_t)r0, (uint32_t)j0);
            if (fabsf(acc[mi][ni][1]) < tA) enqueue((uint32_t)r0, (uint32_t)(j0 + 1));
            if (fabsf(acc[mi][ni][2]) < tB) enqueue((uint32_t)r1, (uint32_t)j0);
            if (fabsf(acc[mi][ni][3]) < tB) enqueue((uint32_t)r1, (uint32_t)(j0 + 1));
        }
    }
}

// --- fixup: recompute ambiguous signs in exact fp32 (warp per queue entry) ---
__global__ __launch_bounds__(256) void fixup_kernel(const float* __restrict__ keys,
                                                    const float* __restrict__ cb,
                                                    const float* __restrict__ S) {
    int lane = threadIdx.x & 31;
    int w = (blockIdx.x * blockDim.x + threadIdx.x) >> 5;
    int nw = (gridDim.x * blockDim.x) >> 5;
    int cnt = g_qcount;
    if (cnt > MAXQ) cnt = MAXQ;
    float c0 = cb[0], c1 = cb[1], c2 = cb[2], c3 = cb[3];
    float m01 = 0.5f * (c0 + c1), m12 = 0.5f * (c1 + c2), m23 = 0.5f * (c2 + c3);

    for (int e = w; e < cnt; e += nw) {
        uint32_t pk = g_queue[e];
        size_t n = (size_t)(pk >> 7);
        uint32_t j = pk & 127u;
        float4 kv = *(const float4*)(keys + n * DDIM + lane * 4);
        float ss = kv.x * kv.x + kv.y * kv.y + kv.z * kv.z + kv.w * kv.w;
#pragma unroll
        for (int o = 16; o; o >>= 1) ss += __shfl_xor_sync(0xffffffffu, ss, o);
        float vn = sqrtf(ss);
        float inv = 1.f / (vn + 1e-8f);
        float x[4] = {kv.x * inv, kv.y * inv, kv.z * inv, kv.w * inv};
        float4 sv = *(const float4*)(S + (size_t)j * DDIM + lane * 4);
        float svv[4] = {sv.x, sv.y, sv.z, sv.w};
        float dot = 0.f;
#pragma unroll
        for (int i = 0; i < 4; i++) {
            float xm = (x[i] >= m12) ? ((x[i] >= m23) ? c3 : c2)
                                     : ((x[i] >= m01) ? c1 : c0);
            dot += (x[i] - xm) * svv[i];
        }
#pragma unroll
        for (int o = 16; o; o >>= 1) dot += __shfl_xor_sync(0xffffffffu, dot, o);
        if (lane == 0) {
            float coef = g_C[n];
            float v = (dot >= 0.f) ? coef : -coef;
            __nv_bfloat16 h, l;
            bf16split(v, h, l);
            g_Bh[n * KTOT + 128 + j] = h;
            g_Bl[n * KTOT + 128 + j] = l;
        }
    }
}

// --- main GEMM: out(512x131072) = A @ B^T, 3-term split, occ 2 ---
#define ROWB 80
#define ARR  10240
#define STG  40960

__global__ __launch_bounds__(256, 2) void gemm_kernel(float* __restrict__ out) {
    extern __shared__ __align__(16) char sm[];
    uint32_t sb = smem_u32(sm);
    int tid = threadIdx.x, wid = tid >> 5, lane = tid & 31;
    int wm = wid >> 2, wn = wid & 3;
    size_t q0 = (size_t)blockIdx.x * 128;
    size_t n0 = (size_t)blockIdx.y * 128;

    float acc[4][4][4];
#pragma unroll
    for (int i = 0; i < 4; i++)
#pragma unroll
        for (int j = 0; j < 4; j++)
#pragma unroll
            for (int k = 0; k < 4; k++) acc[i][j][k] = 0.f;

#define LOAD_STAGE(KC, S_)                                                    \
    do {                                                                      \
        uint32_t stg_ = sb + (S_) * STG;                                      \
        int kofs_ = (KC) * 32;                                                \
        _Pragma("unroll")                                                     \
        for (int it = 0; it < 2; it++) {                                      \
            int idx = tid + it * 256;                                         \
            int row = idx >> 2, c16 = idx & 3;                                \
            uint32_t d = (uint32_t)(row * ROWB + c16 * 16);                   \
            size_t ao = (q0 + (size_t)row) * KTOT + kofs_ + c16 * 8;          \
            cp_async16(stg_ + d,           g_Ah + ao);                        \
            cp_async16(stg_ + ARR + d,     g_Al + ao);                        \
            size_t bo = (n0 + (size_t)row) * KTOT + kofs_ + c16 * 8;          \
            cp_async16(stg_ + 2 * ARR + d, g_Bh + bo);                        \
            cp_async16(stg_ + 3 * ARR + d, g_Bl + bo);                        \
        }                                                                     \
        CP_COMMIT();                                                          \
    } while (0)

    LOAD_STAGE(0, 0);
    int lr = lane & 15, lc = (lane >> 4) * 8;

    for (int kc = 0; kc < 8; kc++) {
        if (kc < 7) { LOAD_STAGE(kc + 1, (kc + 1) & 1); CP_WAIT1(); }
        else        { CP_WAIT0(); }
        __syncthreads();
        uint32_t stg = sb + (kc & 1) * STG;
#pragma unroll
        for (int ks = 0; ks < 2; ks++) {
            uint32_t coff = (uint32_t)((ks * 16 + lc) * 2);
            uint32_t bh[8], bl[8];
#pragma unroll
            for (int h = 0; h < 2; h++) {
                uint32_t bd = stg + 2 * ARR + (uint32_t)((wn * 32 + h * 16 + lr) * ROWB) + coff;
                ldsm4(bh[h * 4 + 0], bh[h * 4 + 1], bh[h * 4 + 2], bh[h * 4 + 3], bd);
                ldsm4(bl[h * 4 + 0], bl[h * 4 + 1], bl[h * 4 + 2], bl[h * 4 + 3], bd + ARR);
            }
#pragma unroll
            for (int mi = 0; mi < 4; mi++) {
                uint32_t ad = stg + (uint32_t)((wm * 64 + mi * 16 + lr) * ROWB) + coff;
                uint32_t ah0, ah1, ah2, ah3, al0, al1, al2, al3;
                ldsm4(ah0, ah1, ah2, ah3, ad);
                ldsm4(al0, al1, al2, al3, ad + ARR);
#pragma unroll
                for (int ni = 0; ni < 4; ni++) {
                    int h = ni >> 1, s2 = ni & 1;
                    uint32_t b0h = bh[h * 4 + s2], b1h = bh[h * 4 + s2 + 2];
                    uint32_t b0l = bl[h * 4 + s2], b1l = bl[h * 4 + s2 + 2];
                    mma16816(acc[mi][ni], ah0, ah1, ah2, ah3, b0h, b1h);
                    mma16816(acc[mi][ni], al0, al1, al2, al3, b0h, b1h);
                    mma16816(acc[mi][ni], ah0, ah1, ah2, ah3, b0l, b1l);
                }
            }
        }
        __syncthreads();
    }

    int g = lane >> 2, tc = lane & 3;
#pragma unroll
    for (int mi = 0; mi < 4; mi++) {
        size_t r0 = q0 + (size_t)(wm * 64 + mi * 16 + g);
        size_t r1 = r0 + 8;
#pragma unroll
        for (int ni = 0; ni < 4; ni++) {
            size_t col = n0 + (size_t)(wn * 32 + ni * 8 + tc * 2);
            *(float2*)(out + r0 * NKEYS + col) = make_float2(acc[mi][ni][0], acc[mi][ni][1]);
            *(float2*)(out + r1 * NKEYS + col) = make_float2(acc[mi][ni][2], acc[mi][ni][3]);
        }
    }
}

extern "C" void kernel_launch(void* const* d_in, const int* in_sizes, int n_in,
                              void* d_out, int out_size) {
    const float* query    = (const float*)d_in[0];
    const float* keys     = (const float*)d_in[1];
    const float* codebook = (const float*)d_in[2];
    const float* S        = (const float*)d_in[3];
    float* out = (float*)d_out;

    zeroq_kernel<<<1, 32>>>();
    build_S_kernel<<<64, 256>>>(S);

    int shA = (128 * 129 + 256) * 4;
    cudaFuncSetAttribute(build_A_kernel, cudaFuncAttributeMaxDynamicSharedMemorySize, shA);
    build_A_kernel<<<64, 256, shA>>>(query, S);

    prep1_kernel<<<NKEYS / 8, 256>>>(keys, codebook);

    int shP = 4 * PARR;  // 139264
    cudaFuncSetAttribute(proj_kernel, cudaFuncAttributeMaxDynamicSharedMemorySize, shP);
    proj_kernel<<<NKEYS / 128, 256, shP>>>();

    fixup_kernel<<<256, 256>>>(keys, codebook, S);

    int shG = 2 * STG;   // 81920
    cudaFuncSetAttribute(gemm_kernel, cudaFuncAttributeMaxDynamicSharedMemorySize, shG);
    dim3 grid(QDIM / 128, NKEYS / 128);
    gemm_kernel<<<grid, 256, shG>>>(out);
}